// round 1
// baseline (speedup 1.0000x reference)
#include <cuda_runtime.h>

// Problem constants
#define KSZ   2
#define CIN   3
#define COUT  16
#define HIN   256
#define WIN   256
#define HF    255      // conv output H/W (VALID)
#define WF    255
#define HO    254      // window output H/W
#define WO    254
#define BATCH 64
#define NPIX  (BATCH * HF * WF)   // 4,161,600 feat pixels
#define BN_EPS 1e-5f

// conv weights, layout [co][ci][kh][kw] flattened: co*12 + ci*4 + kh*2 + kw
__constant__ float c_w[COUT * CIN * KSZ * KSZ];

// per-launch scratch (device globals: no allocation allowed)
__device__ double g_acc[2 * COUT];   // [0..15] = sum(conv), [16..31] = sum(conv^2)
__device__ float  g_scale[COUT];
__device__ float  g_shift[COUT];

// ---------------------------------------------------------------------------
// Kernel 0: zero the accumulators (graph replays reuse them)
// ---------------------------------------------------------------------------
__global__ void zero_acc_kernel() {
    int t = threadIdx.x;
    if (t < 2 * COUT) g_acc[t] = 0.0;
}

// ---------------------------------------------------------------------------
// Kernel 1: per-channel sum / sumsq of the (bias-free) conv output.
// Grid-stride over feat pixels; consecutive threads take consecutive j
// (coalesced, heavy L1 reuse of the overlapping 2x2 taps).
// ---------------------------------------------------------------------------
__global__ void stats_kernel(const float* __restrict__ x) {
    float s[COUT], sq[COUT];
#pragma unroll
    for (int c = 0; c < COUT; c++) { s[c] = 0.f; sq[c] = 0.f; }

    const int stride = gridDim.x * blockDim.x;
    for (int idx = blockIdx.x * blockDim.x + threadIdx.x; idx < NPIX; idx += stride) {
        const int b   = idx / (HF * WF);
        const int rem = idx % (HF * WF);
        const int i   = rem / WF;
        const int j   = rem % WF;
        const float* xb = x + (long long)b * CIN * HIN * WIN;

        float xv[12];
#pragma unroll
        for (int ci = 0; ci < CIN; ci++) {
            const float* p = xb + (ci * HIN + i) * WIN + j;
            xv[ci * 4 + 0] = __ldg(p);
            xv[ci * 4 + 1] = __ldg(p + 1);
            xv[ci * 4 + 2] = __ldg(p + WIN);
            xv[ci * 4 + 3] = __ldg(p + WIN + 1);
        }
#pragma unroll
        for (int c = 0; c < COUT; c++) {
            float v = 0.f;
#pragma unroll
            for (int k = 0; k < 12; k++) v = fmaf(c_w[c * 12 + k], xv[k], v);
            s[c]  += v;
            sq[c]  = fmaf(v, v, sq[c]);
        }
    }

    // warp butterfly reduce each of the 32 accumulators
    const unsigned m = 0xffffffffu;
#pragma unroll
    for (int c = 0; c < COUT; c++) {
        float a = s[c];
#pragma unroll
        for (int o = 16; o > 0; o >>= 1) a += __shfl_xor_sync(m, a, o);
        s[c] = a;
        float bb = sq[c];
#pragma unroll
        for (int o = 16; o > 0; o >>= 1) bb += __shfl_xor_sync(m, bb, o);
        sq[c] = bb;
    }

    __shared__ float sred[8][32];
    const int warp = threadIdx.x >> 5, lane = threadIdx.x & 31;
    if (lane == 0) {
#pragma unroll
        for (int c = 0; c < COUT; c++) {
            sred[warp][c]        = s[c];
            sred[warp][16 + c]   = sq[c];
        }
    }
    __syncthreads();
    if (threadIdx.x < 32) {
        float tot = 0.f;
        const int nw = blockDim.x >> 5;
        for (int w = 0; w < nw; w++) tot += sred[w][threadIdx.x];
        atomicAdd(&g_acc[threadIdx.x], (double)tot);
    }
}

// ---------------------------------------------------------------------------
// Kernel 2: fold BN into per-channel scale/shift.
// feat = conv + cb; BN(feat) = (conv - mean_conv)*scale + beta  (bias cancels)
// ---------------------------------------------------------------------------
__global__ void finalize_kernel(const float* __restrict__ gamma,
                                const float* __restrict__ beta) {
    int c = threadIdx.x;
    if (c >= COUT) return;
    const double N = (double)NPIX;
    double mean = g_acc[c] / N;
    double var  = g_acc[COUT + c] / N - mean * mean;
    float scale = gamma[c] * rsqrtf((float)var + BN_EPS);
    g_scale[c] = scale;
    g_shift[c] = beta[c] - (float)mean * scale;
}

// ---------------------------------------------------------------------------
// Kernel 3: fused conv + BN + relu + tanh + channel-sum + 2x2 window mean.
// Block = 256 threads, computes a 16x16 output tile for one batch image.
// Needs a 17x17 feat tile -> an 18x18 x-tile per input channel in smem.
// ---------------------------------------------------------------------------
__global__ void __launch_bounds__(256) fused_out_kernel(const float* __restrict__ x,
                                                        float* __restrict__ out) {
    __shared__ float sx[CIN][18][18];
    __shared__ float st[17][17];
    __shared__ float ssc[COUT], ssh[COUT];

    const int b   = blockIdx.z;
    const int oy0 = blockIdx.y * 16;
    const int ox0 = blockIdx.x * 16;
    const int tid = threadIdx.x;

    if (tid < COUT) { ssc[tid] = g_scale[tid]; ssh[tid] = g_shift[tid]; }

    const float* xb = x + (long long)b * CIN * HIN * WIN;
    for (int idx = tid; idx < CIN * 18 * 18; idx += 256) {
        const int c   = idx / 324;
        const int rem = idx % 324;
        const int r   = rem / 18;
        const int col = rem % 18;
        const int gr = oy0 + r, gc = ox0 + col;
        float v = 0.f;
        if (gr < HIN && gc < WIN) v = __ldg(&xb[(c * HIN + gr) * WIN + gc]);
        sx[c][r][col] = v;
    }
    __syncthreads();

    for (int p = tid; p < 17 * 17; p += 256) {
        const int fy = p / 17, fx = p % 17;
        float acc = 0.f;
        if (oy0 + fy < HF && ox0 + fx < WF) {
            float xv[12];
#pragma unroll
            for (int ci = 0; ci < CIN; ci++) {
                xv[ci * 4 + 0] = sx[ci][fy][fx];
                xv[ci * 4 + 1] = sx[ci][fy][fx + 1];
                xv[ci * 4 + 2] = sx[ci][fy + 1][fx];
                xv[ci * 4 + 3] = sx[ci][fy + 1][fx + 1];
            }
#pragma unroll
            for (int c = 0; c < COUT; c++) {
                float v = 0.f;
#pragma unroll
                for (int k = 0; k < 12; k++) v = fmaf(c_w[c * 12 + k], xv[k], v);
                v = fmaf(v, ssc[c], ssh[c]);
                v = fmaxf(v, 0.f);
                acc += tanhf(v);
            }
        }
        st[fy][fx] = acc;
    }
    __syncthreads();

    const int ty = tid >> 4, tx = tid & 15;
    const int oi = oy0 + ty, oj = ox0 + tx;
    if (oi < HO && oj < WO) {
        const float r = (st[ty][tx] + st[ty][tx + 1] +
                         st[ty + 1][tx] + st[ty + 1][tx + 1]) *
                        (1.0f / (COUT * KSZ * KSZ));
        out[((long long)b * HO + oi) * WO + oj] = r;
    }
}

// ---------------------------------------------------------------------------
// kernel_launch: inputs per metadata order: x, conv_w, conv_b, gamma, beta
// ---------------------------------------------------------------------------
extern "C" void kernel_launch(void* const* d_in, const int* in_sizes, int n_in,
                              void* d_out, int out_size) {
    const float* x      = (const float*)d_in[0];
    const float* conv_w = (const float*)d_in[1];
    // d_in[2] = conv_b: cancels exactly under training-mode BN, unused.
    const float* gamma  = (const float*)d_in[3];
    const float* beta   = (const float*)d_in[4];
    float* out = (float*)d_out;

    // weights into constant memory (D2D async memcpy: graph-capturable)
    cudaMemcpyToSymbolAsync(c_w, conv_w, COUT * CIN * KSZ * KSZ * sizeof(float),
                            0, cudaMemcpyDeviceToDevice, 0);

    zero_acc_kernel<<<1, 64>>>();

    const int threads = 256;
    const int blocks  = 148 * 4;   // grid-stride covers all pixels
    stats_kernel<<<blocks, threads>>>(x);

    finalize_kernel<<<1, COUT>>>(gamma, beta);

    dim3 grid((WO + 15) / 16, (HO + 15) / 16, BATCH);   // 16 x 16 x 64
    fused_out_kernel<<<grid, 256>>>(x, out);
}